// round 6
// baseline (speedup 1.0000x reference)
#include <cuda_runtime.h>
#include <cstdint>

// WaveGNN: B=16, N=2048, D=128, L=3
//   per layer: hw = h @ W ; agg = adj^T @ hw ; h = relu(LN(agg + b + h))
// agg GEMM on tensor cores via generic-target mma.sync tf32 (m16n8k8).
// R6: 512-thread CTAs (16 warps), conflict-free smem strides, 4-stage pipe.

#define BATCH 16
#define NN    2048
#define DD    128
#define BK    16

// gcn tiling
#define CTJ   256          // j rows per CTA
#define KC    32           // K (i) rows per pipeline chunk
#define NKC   (NN / KC)    // 64 chunks
#define ASTR  264          // adj tile stride  (264 % 32 == 8 -> conflict-free)
#define BSTR  136          // hw  tile stride  (136 % 32 == 8 -> conflict-free)
#define STG_F (KC * ASTR + KC * BSTR)      // floats per stage = 12800
#define NSTG  4
#define DYN_SMEM (NSTG * STG_F * 4)        // 204800 bytes

typedef unsigned long long u64;

// ---------------- scratch (static device globals; no runtime alloc) --------
__device__ float g_hw[BATCH * NN * DD];
__device__ float g_h0[BATCH * NN * DD];
__device__ float g_h1[BATCH * NN * DD];

// ---------------- helpers ---------------------------------------------------
__device__ __forceinline__ uint32_t smem_u32(const void* p) {
    uint32_t a;
    asm("{ .reg .u64 t; cvta.to.shared.u64 t, %1; cvt.u32.u64 %0, t; }"
        : "=r"(a) : "l"(p));
    return a;
}

__device__ __forceinline__ void cpa16(uint32_t dst, const void* src) {
    asm volatile("cp.async.cg.shared.global [%0], [%1], 16;"
                 :: "r"(dst), "l"(src) : "memory");
}
#define CPA_COMMIT() asm volatile("cp.async.commit_group;" ::: "memory")
#define CPA_WAIT2()  asm volatile("cp.async.wait_group 2;" ::: "memory")
#define CPA_WAIT0()  asm volatile("cp.async.wait_group 0;" ::: "memory")

__device__ __forceinline__ void mma_tf32(float* d, const uint32_t* a,
                                         const uint32_t* b) {
    asm volatile(
        "mma.sync.aligned.m16n8k8.row.col.f32.tf32.tf32.f32 "
        "{%0,%1,%2,%3}, {%4,%5,%6,%7}, {%8,%9}, {%0,%1,%2,%3};"
        : "+f"(d[0]), "+f"(d[1]), "+f"(d[2]), "+f"(d[3])
        : "r"(a[0]), "r"(a[1]), "r"(a[2]), "r"(a[3]), "r"(b[0]), "r"(b[1]));
}

__device__ __forceinline__ float tf32_rna(float v) {
    uint32_t u;
    asm("cvt.rna.tf32.f32 %0, %1;" : "=r"(u) : "f"(v));
    return __uint_as_float(u);
}

// f32x2 helpers for the SIMT linear kernel
__device__ __forceinline__ u64 pk2(float x, float y) {
    u64 r; asm("mov.b64 %0,{%1,%2};" : "=l"(r) : "f"(x), "f"(y)); return r;
}
__device__ __forceinline__ void upk2(float& x, float& y, u64 v) {
    asm("mov.b64 {%0,%1},%2;" : "=f"(x), "=f"(y) : "l"(v));
}
__device__ __forceinline__ void ffma2(u64& c, u64 a, u64 b) {
    asm("fma.rn.f32x2 %0,%1,%2,%0;" : "+l"(c) : "l"(a), "l"(b));
}

// ---------------------------------------------------------------------------
// linear_kernel: hw[m,n] = sum_k h[m,k] * W[k,n]; output pre-rounded to tf32
// ---------------------------------------------------------------------------
__device__ __forceinline__ void mma_tile_s(const float* As, const float* Bs,
                                           u64 (*acc)[4], int tx, int ty) {
#pragma unroll
    for (int k = 0; k < BK; k++) {
        const float* ar = As + k * 132 + ty * 8;
        const float* br = Bs + k * 128 + tx * 8;
        float4 a0 = *(const float4*)ar;
        float4 a1 = *(const float4*)(ar + 4);
        float4 b0 = *(const float4*)br;
        float4 b1 = *(const float4*)(br + 4);
        float av[8] = {a0.x, a0.y, a0.z, a0.w, a1.x, a1.y, a1.z, a1.w};
        u64 bb[4] = {pk2(b0.x, b0.y), pk2(b0.z, b0.w),
                     pk2(b1.x, b1.y), pk2(b1.z, b1.w)};
#pragma unroll
        for (int mm = 0; mm < 8; mm++) {
            u64 ap = pk2(av[mm], av[mm]);
#pragma unroll
            for (int nq = 0; nq < 4; nq++) ffma2(acc[mm][nq], ap, bb[nq]);
        }
    }
}

__global__ void __launch_bounds__(256, 2)
linear_kernel(const float* __restrict__ h, const float* __restrict__ W,
              float* __restrict__ out) {
    __shared__ float As[2][BK][132];
    __shared__ float Bs[2][BK][128];

    int tid = threadIdx.x;
    int tx = tid & 15, ty = tid >> 4;
    int m0 = blockIdx.x * 128;

    u64 acc[8][4];
#pragma unroll
    for (int i = 0; i < 8; i++)
#pragma unroll
        for (int j = 0; j < 4; j++) acc[i][j] = 0ull;

    float4 pa[2], pb[2];
#pragma unroll
    for (int p = 0; p < 2; p++) {
        int idx4 = tid + p * 256;
        int am = idx4 >> 2, akg = (idx4 & 3) * 4;
        pa[p] = *(const float4*)(h + (size_t)(m0 + am) * DD + akg);
        int bk = (tid >> 5) + p * 8, bn = (tid & 31) * 4;
        pb[p] = *(const float4*)(W + (size_t)bk * DD + bn);
    }
#pragma unroll
    for (int p = 0; p < 2; p++) {
        int idx4 = tid + p * 256;
        int am = idx4 >> 2, akg = (idx4 & 3) * 4;
        As[0][akg + 0][am] = pa[p].x;
        As[0][akg + 1][am] = pa[p].y;
        As[0][akg + 2][am] = pa[p].z;
        As[0][akg + 3][am] = pa[p].w;
        int bk = (tid >> 5) + p * 8, bn = (tid & 31) * 4;
        *(float4*)&Bs[0][bk][bn] = pb[p];
    }
    __syncthreads();

    const int NK = DD / BK;
    for (int kt = 0; kt < NK; kt++) {
        int cur = kt & 1;
        if (kt + 1 < NK) {
            int k0 = (kt + 1) * BK;
#pragma unroll
            for (int p = 0; p < 2; p++) {
                int idx4 = tid + p * 256;
                int am = idx4 >> 2, akg = (idx4 & 3) * 4;
                pa[p] = *(const float4*)(h + (size_t)(m0 + am) * DD + k0 + akg);
                int bk = (tid >> 5) + p * 8, bn = (tid & 31) * 4;
                pb[p] = *(const float4*)(W + (size_t)(k0 + bk) * DD + bn);
            }
        }
        mma_tile_s(&As[cur][0][0], &Bs[cur][0][0], acc, tx, ty);
        if (kt + 1 < NK) {
            int nxt = cur ^ 1;
#pragma unroll
            for (int p = 0; p < 2; p++) {
                int idx4 = tid + p * 256;
                int am = idx4 >> 2, akg = (idx4 & 3) * 4;
                As[nxt][akg + 0][am] = pa[p].x;
                As[nxt][akg + 1][am] = pa[p].y;
                As[nxt][akg + 2][am] = pa[p].z;
                As[nxt][akg + 3][am] = pa[p].w;
                int bk = (tid >> 5) + p * 8, bn = (tid & 31) * 4;
                *(float4*)&Bs[nxt][bk][bn] = pb[p];
            }
            __syncthreads();
        }
    }

    float* outp = out + (size_t)(m0 + ty * 8) * DD + tx * 8;
#pragma unroll
    for (int mm = 0; mm < 8; mm++) {
        float o[8];
        upk2(o[0], o[1], acc[mm][0]);
        upk2(o[2], o[3], acc[mm][1]);
        upk2(o[4], o[5], acc[mm][2]);
        upk2(o[6], o[7], acc[mm][3]);
        float4 v0, v1;
        v0.x = tf32_rna(o[0]); v0.y = tf32_rna(o[1]);
        v0.z = tf32_rna(o[2]); v0.w = tf32_rna(o[3]);
        v1.x = tf32_rna(o[4]); v1.y = tf32_rna(o[5]);
        v1.z = tf32_rna(o[6]); v1.w = tf32_rna(o[7]);
        *(float4*)(outp + (size_t)mm * DD) = v0;
        *(float4*)(outp + (size_t)mm * DD + 4) = v1;
    }
}

// ---------------------------------------------------------------------------
// gcn_kernel (tf32 mma.sync):
//   D[j,e] = sum_i adj[b,i,j] * hw[b,i,e]  (A gathered transposed from smem)
//   out = relu(LN(D + bias + hin))
// grid (NN/CTJ=8, BATCH) x 512 threads (16 warps, warp tile 64x32, 4x4 grid)
// ---------------------------------------------------------------------------
__global__ void __launch_bounds__(512, 1)
gcn_kernel(const float* __restrict__ adj, const float* __restrict__ hw,
           const float* __restrict__ hin, float* __restrict__ hout,
           const float* __restrict__ bias, const float* __restrict__ gamma,
           const float* __restrict__ beta) {
    extern __shared__ float smem[];
    __shared__ float red_s[CTJ][4][2];
    __shared__ float bias_s[DD], gamma_s[DD], beta_s[DD];

    const int tid = threadIdx.x;
    const int lane = tid & 31;
    const int wid = tid >> 5;
    const int warp_m = wid & 3;      // 4 m-warps x 64 rows
    const int warp_n = wid >> 2;     // 4 n-warps x 32 cols
    const int qm = lane >> 2;        // 0..7
    const int qn = lane & 3;         // 0..3
    const int b = blockIdx.y;
    const int j0 = blockIdx.x * CTJ;

    if (tid < DD) {
        bias_s[tid] = bias[tid];
        gamma_s[tid] = gamma[tid];
        beta_s[tid] = beta[tid];
    }

    const float* adj_b = adj + (size_t)b * NN * NN;
    const float* hw_b = hw + (size_t)b * NN * DD;
    const uint32_t smem_b = smem_u32(smem);

    float d[4][4][4];
#pragma unroll
    for (int mt = 0; mt < 4; mt++)
#pragma unroll
        for (int nt = 0; nt < 4; nt++)
#pragma unroll
            for (int c = 0; c < 4; c++) d[mt][nt][c] = 0.f;

    // ---- chunk loader (cp.async), 512 threads -----------------------------
    auto load_chunk = [&](int kt, int s) {
        uint32_t a_base = smem_b + (uint32_t)(s * STG_F) * 4;
        uint32_t b_base = a_base + (uint32_t)(KC * ASTR) * 4;
        const float* asrc = adj_b + (size_t)(kt * KC) * NN + j0;
        const float* bsrc = hw_b + (size_t)(kt * KC) * DD;
#pragma unroll
        for (int p = 0; p < 4; p++) {             // adj tile: 32 x 256
            int v = tid + p * 512;
            int r = v >> 6, c4 = (v & 63) * 4;
            cpa16(a_base + (uint32_t)(r * ASTR + c4) * 4,
                  asrc + (size_t)r * NN + c4);
        }
#pragma unroll
        for (int p = 0; p < 2; p++) {             // hw tile: 32 x 128
            int v = tid + p * 512;
            int r = v >> 5, c4 = (v & 31) * 4;
            cpa16(b_base + (uint32_t)(r * BSTR + c4) * 4,
                  bsrc + (size_t)r * DD + c4);
        }
        CPA_COMMIT();
    };

    load_chunk(0, 0);
    load_chunk(1, 1);
    load_chunk(2, 2);

    for (int kt = 0; kt < NKC; kt++) {
        CPA_WAIT2();
        __syncthreads();
        if (kt + 3 < NKC) load_chunk(kt + 3, (kt + 3) & (NSTG - 1));

        const float* As = smem + (size_t)(kt & (NSTG - 1)) * STG_F;
        const float* Bs = As + KC * ASTR;
        const uint32_t* Asu = (const uint32_t*)As;
        const uint32_t* Bsu = (const uint32_t*)Bs;

#pragma unroll
        for (int kk = 0; kk < KC / 8; kk++) {
            const int krow = kk * 8 + qn;
            const uint32_t* bp = Bsu + krow * BSTR + warp_n * 32 + qm;
            uint32_t bf[4][2];
#pragma unroll
            for (int nt = 0; nt < 4; nt++) {
                bf[nt][0] = bp[nt * 8];
                bf[nt][1] = bp[4 * BSTR + nt * 8];
            }
            const uint32_t* ap = Asu + krow * ASTR + warp_m * 64 + qm;
#pragma unroll
            for (int mt = 0; mt < 4; mt++) {
                uint32_t af[4];
                const uint32_t* a0 = ap + mt * 16;
                af[0] = a0[0];
                af[1] = a0[8];
                af[2] = a0[4 * ASTR];
                af[3] = a0[4 * ASTR + 8];
#pragma unroll
                for (int nt = 0; nt < 4; nt++) mma_tf32(d[mt][nt], af, bf[nt]);
            }
        }
    }
    CPA_WAIT0();

    // ---- epilogue: z = D + bias + res ; LN ; relu ; store -----------------
    const float* hin_b = hin + ((size_t)b * NN + j0) * DD;
    float* hout_b = hout + ((size_t)b * NN + j0) * DD;

#pragma unroll
    for (int mt = 0; mt < 4; mt++)
#pragma unroll
        for (int h = 0; h < 2; h++) {
            int jl = warp_m * 64 + mt * 16 + h * 8 + qm;
            const float* rrow = hin_b + (size_t)jl * DD;
            float s = 0.f, q = 0.f;
#pragma unroll
            for (int nt = 0; nt < 4; nt++) {
                int e = warp_n * 32 + nt * 8 + qn * 2;
                float2 rv = *(const float2*)(rrow + e);
                float z0 = d[mt][nt][2 * h + 0] + bias_s[e + 0] + rv.x;
                float z1 = d[mt][nt][2 * h + 1] + bias_s[e + 1] + rv.y;
                d[mt][nt][2 * h + 0] = z0;
                d[mt][nt][2 * h + 1] = z1;
                s += z0 + z1;
                q += z0 * z0 + z1 * z1;
            }
            s += __shfl_xor_sync(0xffffffffu, s, 1);
            s += __shfl_xor_sync(0xffffffffu, s, 2);
            q += __shfl_xor_sync(0xffffffffu, q, 1);
            q += __shfl_xor_sync(0xffffffffu, q, 2);
            if (qn == 0) {
                red_s[jl][warp_n][0] = s;
                red_s[jl][warp_n][1] = q;
            }
        }
    __syncthreads();

#pragma unroll
    for (int mt = 0; mt < 4; mt++)
#pragma unroll
        for (int h = 0; h < 2; h++) {
            int jl = warp_m * 64 + mt * 16 + h * 8 + qm;
            float s = red_s[jl][0][0] + red_s[jl][1][0] +
                      red_s[jl][2][0] + red_s[jl][3][0];
            float q = red_s[jl][0][1] + red_s[jl][1][1] +
                      red_s[jl][2][1] + red_s[jl][3][1];
            float mu = s * (1.0f / DD);
            float var = q * (1.0f / DD) - mu * mu;
            float rstd = rsqrtf(var + 1e-5f);
            float* orow = hout_b + (size_t)jl * DD;
#pragma unroll
            for (int nt = 0; nt < 4; nt++) {
                int e = warp_n * 32 + nt * 8 + qn * 2;
                float2 o;
                o.x = fmaxf(0.f, (d[mt][nt][2 * h + 0] - mu) * rstd * gamma_s[e + 0] + beta_s[e + 0]);
                o.y = fmaxf(0.f, (d[mt][nt][2 * h + 1] - mu) * rstd * gamma_s[e + 1] + beta_s[e + 1]);
                *(float2*)(orow + e) = o;
            }
        }
}

// ---------------------------------------------------------------------------
extern "C" void kernel_launch(void* const* d_in, const int* in_sizes, int n_in,
                              void* d_out, int out_size) {
    (void)in_sizes; (void)n_in; (void)out_size;
    const float* X      = (const float*)d_in[0];
    const float* adj    = (const float*)d_in[1];
    const float* Ws     = (const float*)d_in[2];
    const float* bs     = (const float*)d_in[3];
    const float* gammas = (const float*)d_in[4];
    const float* betas  = (const float*)d_in[5];
    float* out = (float*)d_out;

    float *hw, *h0, *h1;
    cudaGetSymbolAddress((void**)&hw, g_hw);
    cudaGetSymbolAddress((void**)&h0, g_h0);
    cudaGetSymbolAddress((void**)&h1, g_h1);

    static int configured = 0;
    if (!configured) {
        cudaFuncSetAttribute(gcn_kernel,
                             cudaFuncAttributeMaxDynamicSharedMemorySize,
                             DYN_SMEM);
        configured = 1;
    }

    const float* hsrc = X;
    for (int l = 0; l < 3; l++) {
        float* hdst = (l == 2) ? out : (l == 0 ? h0 : h1);
        linear_kernel<<<(BATCH * NN) / 128, 256>>>(
            hsrc, Ws + (size_t)l * DD * DD, hw);
        gcn_kernel<<<dim3(NN / CTJ, BATCH), 512, DYN_SMEM>>>(
            adj, hw, hsrc, hdst,
            bs + (size_t)l * DD, gammas + (size_t)l * DD,
            betas + (size_t)l * DD);
        hsrc = hdst;
    }
}

// round 7
// speedup vs baseline: 1.5507x; 1.5507x over previous
#include <cuda_runtime.h>
#include <cstdint>

// WaveGNN: B=16, N=2048, D=128, L=3
//   per layer: hw = h @ W ; agg = adj^T @ hw ; h = relu(LN(agg + b + h))
// agg GEMM on tensor cores via generic-target mma.sync tf32 (m16n8k8).
// R7: CTA tile 128x128, 256 thr (8 warps, warp tile 32x64), smem 104.4KB
//     -> 2 independent CTAs per SM for latency hiding (R6 post-mortem fix).

#define BATCH 16
#define NN    2048
#define DD    128
#define BK    16

// gcn tiling
#define CTJ   128          // j rows per CTA
#define KC    32           // K (i) rows per pipeline chunk
#define NKC   (NN / KC)    // 64 chunks
#define ASTR  136          // adj tile stride (136 % 32 == 8 -> conflict-free)
#define BSTR  136          // hw  tile stride
#define STG_F (KC * ASTR + KC * BSTR)      // floats per stage = 8704
#define NSTG  3
#define DYN_SMEM (NSTG * STG_F * 4)        // 104448 bytes -> 2 CTAs/SM

typedef unsigned long long u64;

// ---------------- scratch (static device globals; no runtime alloc) --------
__device__ float g_hw[BATCH * NN * DD];
__device__ float g_h0[BATCH * NN * DD];
__device__ float g_h1[BATCH * NN * DD];

// ---------------- helpers ---------------------------------------------------
__device__ __forceinline__ uint32_t smem_u32(const void* p) {
    uint32_t a;
    asm("{ .reg .u64 t; cvta.to.shared.u64 t, %1; cvt.u32.u64 %0, t; }"
        : "=r"(a) : "l"(p));
    return a;
}

__device__ __forceinline__ void cpa16(uint32_t dst, const void* src) {
    asm volatile("cp.async.cg.shared.global [%0], [%1], 16;"
                 :: "r"(dst), "l"(src) : "memory");
}
#define CPA_COMMIT() asm volatile("cp.async.commit_group;" ::: "memory")
#define CPA_WAIT1()  asm volatile("cp.async.wait_group 1;" ::: "memory")
#define CPA_WAIT0()  asm volatile("cp.async.wait_group 0;" ::: "memory")

__device__ __forceinline__ void mma_tf32(float* d, const uint32_t* a,
                                         const uint32_t* b) {
    asm volatile(
        "mma.sync.aligned.m16n8k8.row.col.f32.tf32.tf32.f32 "
        "{%0,%1,%2,%3}, {%4,%5,%6,%7}, {%8,%9}, {%0,%1,%2,%3};"
        : "+f"(d[0]), "+f"(d[1]), "+f"(d[2]), "+f"(d[3])
        : "r"(a[0]), "r"(a[1]), "r"(a[2]), "r"(a[3]), "r"(b[0]), "r"(b[1]));
}

__device__ __forceinline__ float tf32_rna(float v) {
    uint32_t u;
    asm("cvt.rna.tf32.f32 %0, %1;" : "=r"(u) : "f"(v));
    return __uint_as_float(u);
}

// f32x2 helpers for the SIMT linear kernel
__device__ __forceinline__ u64 pk2(float x, float y) {
    u64 r; asm("mov.b64 %0,{%1,%2};" : "=l"(r) : "f"(x), "f"(y)); return r;
}
__device__ __forceinline__ void upk2(float& x, float& y, u64 v) {
    asm("mov.b64 {%0,%1},%2;" : "=f"(x), "=f"(y) : "l"(v));
}
__device__ __forceinline__ void ffma2(u64& c, u64 a, u64 b) {
    asm("fma.rn.f32x2 %0,%1,%2,%0;" : "+l"(c) : "l"(a), "l"(b));
}

// ---------------------------------------------------------------------------
// linear_kernel: hw[m,n] = sum_k h[m,k] * W[k,n]; output pre-rounded to tf32
// ---------------------------------------------------------------------------
__device__ __forceinline__ void mma_tile_s(const float* As, const float* Bs,
                                           u64 (*acc)[4], int tx, int ty) {
#pragma unroll
    for (int k = 0; k < BK; k++) {
        const float* ar = As + k * 132 + ty * 8;
        const float* br = Bs + k * 128 + tx * 8;
        float4 a0 = *(const float4*)ar;
        float4 a1 = *(const float4*)(ar + 4);
        float4 b0 = *(const float4*)br;
        float4 b1 = *(const float4*)(br + 4);
        float av[8] = {a0.x, a0.y, a0.z, a0.w, a1.x, a1.y, a1.z, a1.w};
        u64 bb[4] = {pk2(b0.x, b0.y), pk2(b0.z, b0.w),
                     pk2(b1.x, b1.y), pk2(b1.z, b1.w)};
#pragma unroll
        for (int mm = 0; mm < 8; mm++) {
            u64 ap = pk2(av[mm], av[mm]);
#pragma unroll
            for (int nq = 0; nq < 4; nq++) ffma2(acc[mm][nq], ap, bb[nq]);
        }
    }
}

__global__ void __launch_bounds__(256, 2)
linear_kernel(const float* __restrict__ h, const float* __restrict__ W,
              float* __restrict__ out) {
    __shared__ float As[2][BK][132];
    __shared__ float Bs[2][BK][128];

    int tid = threadIdx.x;
    int tx = tid & 15, ty = tid >> 4;
    int m0 = blockIdx.x * 128;

    u64 acc[8][4];
#pragma unroll
    for (int i = 0; i < 8; i++)
#pragma unroll
        for (int j = 0; j < 4; j++) acc[i][j] = 0ull;

    float4 pa[2], pb[2];
#pragma unroll
    for (int p = 0; p < 2; p++) {
        int idx4 = tid + p * 256;
        int am = idx4 >> 2, akg = (idx4 & 3) * 4;
        pa[p] = *(const float4*)(h + (size_t)(m0 + am) * DD + akg);
        int bk = (tid >> 5) + p * 8, bn = (tid & 31) * 4;
        pb[p] = *(const float4*)(W + (size_t)bk * DD + bn);
    }
#pragma unroll
    for (int p = 0; p < 2; p++) {
        int idx4 = tid + p * 256;
        int am = idx4 >> 2, akg = (idx4 & 3) * 4;
        As[0][akg + 0][am] = pa[p].x;
        As[0][akg + 1][am] = pa[p].y;
        As[0][akg + 2][am] = pa[p].z;
        As[0][akg + 3][am] = pa[p].w;
        int bk = (tid >> 5) + p * 8, bn = (tid & 31) * 4;
        *(float4*)&Bs[0][bk][bn] = pb[p];
    }
    __syncthreads();

    const int NK = DD / BK;
    for (int kt = 0; kt < NK; kt++) {
        int cur = kt & 1;
        if (kt + 1 < NK) {
            int k0 = (kt + 1) * BK;
#pragma unroll
            for (int p = 0; p < 2; p++) {
                int idx4 = tid + p * 256;
                int am = idx4 >> 2, akg = (idx4 & 3) * 4;
                pa[p] = *(const float4*)(h + (size_t)(m0 + am) * DD + k0 + akg);
                int bk = (tid >> 5) + p * 8, bn = (tid & 31) * 4;
                pb[p] = *(const float4*)(W + (size_t)(k0 + bk) * DD + bn);
            }
        }
        mma_tile_s(&As[cur][0][0], &Bs[cur][0][0], acc, tx, ty);
        if (kt + 1 < NK) {
            int nxt = cur ^ 1;
#pragma unroll
            for (int p = 0; p < 2; p++) {
                int idx4 = tid + p * 256;
                int am = idx4 >> 2, akg = (idx4 & 3) * 4;
                As[nxt][akg + 0][am] = pa[p].x;
                As[nxt][akg + 1][am] = pa[p].y;
                As[nxt][akg + 2][am] = pa[p].z;
                As[nxt][akg + 3][am] = pa[p].w;
                int bk = (tid >> 5) + p * 8, bn = (tid & 31) * 4;
                *(float4*)&Bs[nxt][bk][bn] = pb[p];
            }
            __syncthreads();
        }
    }

    float* outp = out + (size_t)(m0 + ty * 8) * DD + tx * 8;
#pragma unroll
    for (int mm = 0; mm < 8; mm++) {
        float o[8];
        upk2(o[0], o[1], acc[mm][0]);
        upk2(o[2], o[3], acc[mm][1]);
        upk2(o[4], o[5], acc[mm][2]);
        upk2(o[6], o[7], acc[mm][3]);
        float4 v0, v1;
        v0.x = tf32_rna(o[0]); v0.y = tf32_rna(o[1]);
        v0.z = tf32_rna(o[2]); v0.w = tf32_rna(o[3]);
        v1.x = tf32_rna(o[4]); v1.y = tf32_rna(o[5]);
        v1.z = tf32_rna(o[6]); v1.w = tf32_rna(o[7]);
        *(float4*)(outp + (size_t)mm * DD) = v0;
        *(float4*)(outp + (size_t)mm * DD + 4) = v1;
    }
}

// ---------------------------------------------------------------------------
// gcn_kernel (tf32 mma.sync):
//   D[j,e] = sum_i adj[b,i,j] * hw[b,i,e]  (A gathered transposed from smem)
//   out = relu(LN(D + bias + hin))
// grid (NN/CTJ=16, BATCH) x 256 threads; 8 warps, warp tile 32x64 (4m x 2n)
// ---------------------------------------------------------------------------
__global__ void __launch_bounds__(256, 2)
gcn_kernel(const float* __restrict__ adj, const float* __restrict__ hw,
           const float* __restrict__ hin, float* __restrict__ hout,
           const float* __restrict__ bias, const float* __restrict__ gamma,
           const float* __restrict__ beta) {
    extern __shared__ float smem[];
    __shared__ float red_s[CTJ][2][2];
    __shared__ float bias_s[DD], gamma_s[DD], beta_s[DD];

    const int tid = threadIdx.x;
    const int lane = tid & 31;
    const int wid = tid >> 5;
    const int warp_m = wid & 3;      // 4 m-warps x 32 rows
    const int warp_n = wid >> 2;     // 2 n-warps x 64 cols
    const int qm = lane >> 2;        // 0..7
    const int qn = lane & 3;         // 0..3
    const int b = blockIdx.y;
    const int j0 = blockIdx.x * CTJ;

    if (tid < DD) {
        bias_s[tid] = bias[tid];
        gamma_s[tid] = gamma[tid];
        beta_s[tid] = beta[tid];
    }

    const float* adj_b = adj + (size_t)b * NN * NN;
    const float* hw_b = hw + (size_t)b * NN * DD;
    const uint32_t smem_b = smem_u32(smem);

    float d[2][8][4];
#pragma unroll
    for (int mt = 0; mt < 2; mt++)
#pragma unroll
        for (int nt = 0; nt < 8; nt++)
#pragma unroll
            for (int c = 0; c < 4; c++) d[mt][nt][c] = 0.f;

    // ---- chunk loader (cp.async), 256 threads -----------------------------
    auto load_chunk = [&](int kt, int s) {
        uint32_t a_base = smem_b + (uint32_t)(s * STG_F) * 4;
        uint32_t b_base = a_base + (uint32_t)(KC * ASTR) * 4;
        const float* asrc = adj_b + (size_t)(kt * KC) * NN + j0;
        const float* bsrc = hw_b + (size_t)(kt * KC) * DD;
#pragma unroll
        for (int p = 0; p < 4; p++) {             // adj tile: 32 x 128
            int v = tid + p * 256;
            int r = v >> 5, c4 = (v & 31) * 4;
            cpa16(a_base + (uint32_t)(r * ASTR + c4) * 4,
                  asrc + (size_t)r * NN + c4);
        }
#pragma unroll
        for (int p = 0; p < 4; p++) {             // hw tile: 32 x 128
            int v = tid + p * 256;
            int r = v >> 5, c4 = (v & 31) * 4;
            cpa16(b_base + (uint32_t)(r * BSTR + c4) * 4,
                  bsrc + (size_t)r * DD + c4);
        }
        CPA_COMMIT();
    };

    load_chunk(0, 0);
    load_chunk(1, 1);

    for (int kt = 0; kt < NKC; kt++) {
        CPA_WAIT1();
        __syncthreads();
        if (kt + 2 < NKC) load_chunk(kt + 2, (kt + 2) % NSTG);

        const float* As = smem + (size_t)(kt % NSTG) * STG_F;
        const float* Bs = As + KC * ASTR;
        const uint32_t* Asu = (const uint32_t*)As;
        const uint32_t* Bsu = (const uint32_t*)Bs;

#pragma unroll
        for (int kk = 0; kk < KC / 8; kk++) {
            const int krow = kk * 8 + qn;
            const uint32_t* bp = Bsu + krow * BSTR + warp_n * 64 + qm;
            uint32_t bf[8][2];
#pragma unroll
            for (int nt = 0; nt < 8; nt++) {
                bf[nt][0] = bp[nt * 8];
                bf[nt][1] = bp[4 * BSTR + nt * 8];
            }
            const uint32_t* ap = Asu + krow * ASTR + warp_m * 32 + qm;
#pragma unroll
            for (int mt = 0; mt < 2; mt++) {
                uint32_t af[4];
                const uint32_t* a0 = ap + mt * 16;
                af[0] = a0[0];
                af[1] = a0[8];
                af[2] = a0[4 * ASTR];
                af[3] = a0[4 * ASTR + 8];
#pragma unroll
                for (int nt = 0; nt < 8; nt++) mma_tf32(d[mt][nt], af, bf[nt]);
            }
        }
    }
    CPA_WAIT0();

    // ---- epilogue: z = D + bias + res ; LN ; relu ; store -----------------
    const float* hin_b = hin + ((size_t)b * NN + j0) * DD;
    float* hout_b = hout + ((size_t)b * NN + j0) * DD;

#pragma unroll
    for (int mt = 0; mt < 2; mt++)
#pragma unroll
        for (int h = 0; h < 2; h++) {
            int jl = warp_m * 32 + mt * 16 + h * 8 + qm;
            const float* rrow = hin_b + (size_t)jl * DD;
            float s = 0.f, q = 0.f;
#pragma unroll
            for (int nt = 0; nt < 8; nt++) {
                int e = warp_n * 64 + nt * 8 + qn * 2;
                float2 rv = *(const float2*)(rrow + e);
                float z0 = d[mt][nt][2 * h + 0] + bias_s[e + 0] + rv.x;
                float z1 = d[mt][nt][2 * h + 1] + bias_s[e + 1] + rv.y;
                d[mt][nt][2 * h + 0] = z0;
                d[mt][nt][2 * h + 1] = z1;
                s += z0 + z1;
                q += z0 * z0 + z1 * z1;
            }
            s += __shfl_xor_sync(0xffffffffu, s, 1);
            s += __shfl_xor_sync(0xffffffffu, s, 2);
            q += __shfl_xor_sync(0xffffffffu, q, 1);
            q += __shfl_xor_sync(0xffffffffu, q, 2);
            if (qn == 0) {
                red_s[jl][warp_n][0] = s;
                red_s[jl][warp_n][1] = q;
            }
        }
    __syncthreads();

#pragma unroll
    for (int mt = 0; mt < 2; mt++)
#pragma unroll
        for (int h = 0; h < 2; h++) {
            int jl = warp_m * 32 + mt * 16 + h * 8 + qm;
            float s = red_s[jl][0][0] + red_s[jl][1][0];
            float q = red_s[jl][0][1] + red_s[jl][1][1];
            float mu = s * (1.0f / DD);
            float var = q * (1.0f / DD) - mu * mu;
            float rstd = rsqrtf(var + 1e-5f);
            float* orow = hout_b + (size_t)jl * DD;
#pragma unroll
            for (int nt = 0; nt < 8; nt++) {
                int e = warp_n * 64 + nt * 8 + qn * 2;
                float2 o;
                o.x = fmaxf(0.f, (d[mt][nt][2 * h + 0] - mu) * rstd * gamma_s[e + 0] + beta_s[e + 0]);
                o.y = fmaxf(0.f, (d[mt][nt][2 * h + 1] - mu) * rstd * gamma_s[e + 1] + beta_s[e + 1]);
                *(float2*)(orow + e) = o;
            }
        }
}

// ---------------------------------------------------------------------------
extern "C" void kernel_launch(void* const* d_in, const int* in_sizes, int n_in,
                              void* d_out, int out_size) {
    (void)in_sizes; (void)n_in; (void)out_size;
    const float* X      = (const float*)d_in[0];
    const float* adj    = (const float*)d_in[1];
    const float* Ws     = (const float*)d_in[2];
    const float* bs     = (const float*)d_in[3];
    const float* gammas = (const float*)d_in[4];
    const float* betas  = (const float*)d_in[5];
    float* out = (float*)d_out;

    float *hw, *h0, *h1;
    cudaGetSymbolAddress((void**)&hw, g_hw);
    cudaGetSymbolAddress((void**)&h0, g_h0);
    cudaGetSymbolAddress((void**)&h1, g_h1);

    static int configured = 0;
    if (!configured) {
        cudaFuncSetAttribute(gcn_kernel,
                             cudaFuncAttributeMaxDynamicSharedMemorySize,
                             DYN_SMEM);
        configured = 1;
    }

    const float* hsrc = X;
    for (int l = 0; l < 3; l++) {
        float* hdst = (l == 2) ? out : (l == 0 ? h0 : h1);
        linear_kernel<<<(BATCH * NN) / 128, 256>>>(
            hsrc, Ws + (size_t)l * DD * DD, hw);
        gcn_kernel<<<dim3(NN / CTJ, BATCH), 256, DYN_SMEM>>>(
            adj, hw, hsrc, hdst,
            bs + (size_t)l * DD, gammas + (size_t)l * DD,
            betas + (size_t)l * DD);
        hsrc = hdst;
    }
}

// round 10
// speedup vs baseline: 1.5728x; 1.0143x over previous
#include <cuda_runtime.h>
#include <cstdint>

// WaveGNN: B=16, N=2048, D=128, L=3
//   per layer: hw = h @ W ; agg = adj^T @ hw ; h = relu(LN(agg + b + h))
// agg GEMM on tensor cores via generic-target mma.sync tf32 (m16n8k8).
// R8: hw stored in pre-swizzled B-fragment order -> gcn B loads are 4xLDS.128
//     per k8 (was 16xLDS.32); smem/stage shrinks; 2 CTAs/SM retained.

#define BATCH 16
#define NN    2048
#define DD    128
#define BK    16

// gcn tiling
#define CTJ   128          // j rows per CTA
#define KC    32           // K (i) rows per pipeline chunk
#define NKC   (NN / KC)    // 64 chunks
#define ASTR  136          // adj tile stride (8qn+qm distinct banks)
#define A_FLOATS (KC * ASTR)          // 4352
#define B_FLOATS (KC * DD)            // 4096 (frag layout, no padding)
#define STG_F (A_FLOATS + B_FLOATS)   // 8448 floats/stage
#define NSTG  3
#define DYN_SMEM (NSTG * STG_F * 4)   // 101376 bytes -> 2 CTAs/SM

typedef unsigned long long u64;

// ---------------- scratch (static device globals; no runtime alloc) --------
__device__ float g_hw[BATCH * NN * DD];   // FRAGMENT layout (see below)
__device__ float g_h0[BATCH * NN * DD];
__device__ float g_h1[BATCH * NN * DD];

// hw fragment layout, per batch b, per 32-row i-chunk c:
//   offset = ((b*64 + c) * 4096) + (wn*4 + kk)*512 + lane*16 + ((s4^sw)<<2) + sl
// where for value hw[i][e]:
//   ic=i%32, kk=ic/8, kr=ic%8, qn=kr&3, h=kr>>2
//   wn=e>>6, nl=e&63, qm=nl&7, nt=nl>>3
//   lane=qm*4+qn, s=h*8+nt, s4=s>>2, sl=s&3, sw=(lane>>1)&3
// A lane's 16 floats are exactly its m16n8k8 B-fragments for that k8 group,
// with the 4-float groups XOR-swizzled so smem LDS.128 is conflict-free.

// ---------------- helpers ---------------------------------------------------
__device__ __forceinline__ uint32_t smem_u32(const void* p) {
    uint32_t a;
    asm("{ .reg .u64 t; cvta.to.shared.u64 t, %1; cvt.u32.u64 %0, t; }"
        : "=r"(a) : "l"(p));
    return a;
}

__device__ __forceinline__ void cpa16(uint32_t dst, const void* src) {
    asm volatile("cp.async.cg.shared.global [%0], [%1], 16;"
                 :: "r"(dst), "l"(src) : "memory");
}
#define CPA_COMMIT() asm volatile("cp.async.commit_group;" ::: "memory")
#define CPA_WAIT1()  asm volatile("cp.async.wait_group 1;" ::: "memory")
#define CPA_WAIT0()  asm volatile("cp.async.wait_group 0;" ::: "memory")

__device__ __forceinline__ void mma_tf32(float* d, const uint32_t* a,
                                         const uint32_t b0, const uint32_t b1) {
    asm volatile(
        "mma.sync.aligned.m16n8k8.row.col.f32.tf32.tf32.f32 "
        "{%0,%1,%2,%3}, {%4,%5,%6,%7}, {%8,%9}, {%0,%1,%2,%3};"
        : "+f"(d[0]), "+f"(d[1]), "+f"(d[2]), "+f"(d[3])
        : "r"(a[0]), "r"(a[1]), "r"(a[2]), "r"(a[3]), "r"(b0), "r"(b1));
}

__device__ __forceinline__ float tf32_rna(float v) {
    uint32_t u;
    asm("cvt.rna.tf32.f32 %0, %1;" : "=r"(u) : "f"(v));
    return __uint_as_float(u);
}

// f32x2 helpers for the SIMT linear kernel
__device__ __forceinline__ u64 pk2(float x, float y) {
    u64 r; asm("mov.b64 %0,{%1,%2};" : "=l"(r) : "f"(x), "f"(y)); return r;
}
__device__ __forceinline__ void upk2(float& x, float& y, u64 v) {
    asm("mov.b64 {%0,%1},%2;" : "=f"(x), "=f"(y) : "l"(v));
}
__device__ __forceinline__ void ffma2(u64& c, u64 a, u64 b) {
    asm("fma.rn.f32x2 %0,%1,%2,%0;" : "+l"(c) : "l"(a), "l"(b));
}

// ---------------------------------------------------------------------------
// linear_kernel: hw[m,n] = sum_k h[m,k] * W[k,n]
// epilogue stores hw in the pre-swizzled B-fragment layout (tf32-rounded).
// ---------------------------------------------------------------------------
__device__ __forceinline__ void mma_tile_s(const float* As, const float* Bs,
                                           u64 (*acc)[4], int tx, int ty) {
#pragma unroll
    for (int k = 0; k < BK; k++) {
        const float* ar = As + k * 132 + ty * 8;
        const float* br = Bs + k * 128 + tx * 8;
        float4 a0 = *(const float4*)ar;
        float4 a1 = *(const float4*)(ar + 4);
        float4 b0 = *(const float4*)br;
        float4 b1 = *(const float4*)(br + 4);
        float av[8] = {a0.x, a0.y, a0.z, a0.w, a1.x, a1.y, a1.z, a1.w};
        u64 bb[4] = {pk2(b0.x, b0.y), pk2(b0.z, b0.w),
                     pk2(b1.x, b1.y), pk2(b1.z, b1.w)};
#pragma unroll
        for (int mm = 0; mm < 8; mm++) {
            u64 ap = pk2(av[mm], av[mm]);
#pragma unroll
            for (int nq = 0; nq < 4; nq++) ffma2(acc[mm][nq], ap, bb[nq]);
        }
    }
}

__global__ void __launch_bounds__(256, 2)
linear_kernel(const float* __restrict__ h, const float* __restrict__ W,
              float* __restrict__ out) {
    __shared__ float As[2][BK][132];
    __shared__ float Bs[2][BK][128];

    int tid = threadIdx.x;
    int tx = tid & 15, ty = tid >> 4;
    int m0 = blockIdx.x * 128;

    u64 acc[8][4];
#pragma unroll
    for (int i = 0; i < 8; i++)
#pragma unroll
        for (int j = 0; j < 4; j++) acc[i][j] = 0ull;

    float4 pa[2], pb[2];
#pragma unroll
    for (int p = 0; p < 2; p++) {
        int idx4 = tid + p * 256;
        int am = idx4 >> 2, akg = (idx4 & 3) * 4;
        pa[p] = *(const float4*)(h + (size_t)(m0 + am) * DD + akg);
        int bk = (tid >> 5) + p * 8, bn = (tid & 31) * 4;
        pb[p] = *(const float4*)(W + (size_t)bk * DD + bn);
    }
#pragma unroll
    for (int p = 0; p < 2; p++) {
        int idx4 = tid + p * 256;
        int am = idx4 >> 2, akg = (idx4 & 3) * 4;
        As[0][akg + 0][am] = pa[p].x;
        As[0][akg + 1][am] = pa[p].y;
        As[0][akg + 2][am] = pa[p].z;
        As[0][akg + 3][am] = pa[p].w;
        int bk = (tid >> 5) + p * 8, bn = (tid & 31) * 4;
        *(float4*)&Bs[0][bk][bn] = pb[p];
    }
    __syncthreads();

    const int NK = DD / BK;
    for (int kt = 0; kt < NK; kt++) {
        int cur = kt & 1;
        if (kt + 1 < NK) {
            int k0 = (kt + 1) * BK;
#pragma unroll
            for (int p = 0; p < 2; p++) {
                int idx4 = tid + p * 256;
                int am = idx4 >> 2, akg = (idx4 & 3) * 4;
                pa[p] = *(const float4*)(h + (size_t)(m0 + am) * DD + k0 + akg);
                int bk = (tid >> 5) + p * 8, bn = (tid & 31) * 4;
                pb[p] = *(const float4*)(W + (size_t)(k0 + bk) * DD + bn);
            }
        }
        mma_tile_s(&As[cur][0][0], &Bs[cur][0][0], acc, tx, ty);
        if (kt + 1 < NK) {
            int nxt = cur ^ 1;
#pragma unroll
            for (int p = 0; p < 2; p++) {
                int idx4 = tid + p * 256;
                int am = idx4 >> 2, akg = (idx4 & 3) * 4;
                As[nxt][akg + 0][am] = pa[p].x;
                As[nxt][akg + 1][am] = pa[p].y;
                As[nxt][akg + 2][am] = pa[p].z;
                As[nxt][akg + 3][am] = pa[p].w;
                int bk = (tid >> 5) + p * 8, bn = (tid & 31) * 4;
                *(float4*)&Bs[nxt][bk][bn] = pb[p];
            }
            __syncthreads();
        }
    }

    // ---- epilogue: scatter-store into B-fragment layout -------------------
#pragma unroll
    for (int mm = 0; mm < 8; mm++) {
        float o[8];
        upk2(o[0], o[1], acc[mm][0]);
        upk2(o[2], o[3], acc[mm][1]);
        upk2(o[4], o[5], acc[mm][2]);
        upk2(o[6], o[7], acc[mm][3]);

        int i_glob = m0 + ty * 8 + mm;
        int b = i_glob >> 11;            // / NN
        int il = i_glob & (NN - 1);
        int chunk = il >> 5;
        int ic = il & 31;
        int kk = ic >> 3;
        int kr = ic & 7;
        int qn_ = kr & 3;
        int hh = kr >> 2;
        size_t cbase = ((size_t)(b * 64 + chunk)) * 4096;

#pragma unroll
        for (int n = 0; n < 8; n++) {
            int e = tx * 8 + n;
            int wn = e >> 6;
            int nt = (e >> 3) & 7;
            int lane = n * 4 + qn_;
            int s = hh * 8 + nt;
            int s4 = s >> 2, sl = s & 3;
            int sw = (lane >> 1) & 3;
            size_t off = cbase + (size_t)((wn * 4 + kk) * 512 + lane * 16 +
                                          ((s4 ^ sw) << 2) + sl);
            out[off] = tf32_rna(o[n]);
        }
    }
}

// ---------------------------------------------------------------------------
// gcn_kernel (tf32 mma.sync):
//   D[j,e] = sum_i adj[b,i,j] * hw[b,i,e]
//   out = relu(LN(D + bias + hin))
// grid (NN/CTJ=16, BATCH) x 256 threads; 8 warps, warp tile 32x64 (4m x 2n)
// B operand read as 4xLDS.128 per k8 from the fragment-layout smem tile.
// ---------------------------------------------------------------------------
__global__ void __launch_bounds__(256, 2)
gcn_kernel(const float* __restrict__ adj, const float* __restrict__ hw,
           const float* __restrict__ hin, float* __restrict__ hout,
           const float* __restrict__ bias, const float* __restrict__ gamma,
           const float* __restrict__ beta) {
    extern __shared__ float smem[];
    __shared__ float red_s[CTJ][2][2];
    __shared__ float bias_s[DD], gamma_s[DD], beta_s[DD];

    const int tid = threadIdx.x;
    const int lane = tid & 31;
    const int wid = tid >> 5;
    const int warp_m = wid & 3;      // 4 m-warps x 32 rows
    const int warp_n = wid >> 2;     // 2 n-warps x 64 cols
    const int qm = lane >> 2;        // 0..7
    const int qn = lane & 3;         // 0..3
    const int sw = (lane >> 1) & 3;  // B-frag xor swizzle
    const int b = blockIdx.y;
    const int j0 = blockIdx.x * CTJ;

    if (tid < DD) {
        bias_s[tid] = bias[tid];
        gamma_s[tid] = gamma[tid];
        beta_s[tid] = beta[tid];
    }

    const float* adj_b = adj + (size_t)b * NN * NN;
    const float* hw_b = hw + (size_t)b * NN * DD;   // frag layout
    const uint32_t smem_b = smem_u32(smem);

    float d[2][8][4];
#pragma unroll
    for (int mt = 0; mt < 2; mt++)
#pragma unroll
        for (int nt = 0; nt < 8; nt++)
#pragma unroll
            for (int c = 0; c < 4; c++) d[mt][nt][c] = 0.f;

    // ---- chunk loader (cp.async), 256 threads -----------------------------
    auto load_chunk = [&](int kt, int s) {
        uint32_t a_base = smem_b + (uint32_t)(s * STG_F) * 4;
        uint32_t b_base = a_base + (uint32_t)A_FLOATS * 4;
        const float* asrc = adj_b + (size_t)(kt * KC) * NN + j0;
        const float* bsrc = hw_b + (size_t)kt * B_FLOATS;
#pragma unroll
        for (int p = 0; p < 4; p++) {             // adj tile: 32 x 128
            int v = tid + p * 256;
            int r = v >> 5, c4 = (v & 31) * 4;
            cpa16(a_base + (uint32_t)(r * ASTR + c4) * 4,
                  asrc + (size_t)r * NN + c4);
        }
#pragma unroll
        for (int p = 0; p < 4; p++) {             // hw tile: contiguous 16KB
            int g = tid + p * 256;
            cpa16(b_base + (uint32_t)g * 16, bsrc + (size_t)g * 4);
        }
        CPA_COMMIT();
    };

    load_chunk(0, 0);
    load_chunk(1, 1);

    for (int kt = 0; kt < NKC; kt++) {
        CPA_WAIT1();
        __syncthreads();
        if (kt + 2 < NKC) load_chunk(kt + 2, (kt + 2) % NSTG);

        const float* As = smem + (size_t)(kt % NSTG) * STG_F;
        const float* Bs = As + A_FLOATS;
        const uint32_t* Asu = (const uint32_t*)As;

#pragma unroll
        for (int kk = 0; kk < KC / 8; kk++) {
            // B fragments: 4 x LDS.128, de-swizzled into logical order
            const float4* bp = (const float4*)(Bs + (warp_n * 4 + kk) * 512 +
                                               lane * 16);
            float4 bq[4];
            bq[0] = bp[0 ^ sw];
            bq[1] = bp[1 ^ sw];
            bq[2] = bp[2 ^ sw];
            bq[3] = bp[3 ^ sw];
            const uint32_t* bu = (const uint32_t*)bq;
            // bu[nt]   = B(k=qn,   n=qm+8nt)
            // bu[8+nt] = B(k=qn+4, n=qm+8nt)

            const int krow = kk * 8 + qn;
            const uint32_t* ap = Asu + krow * ASTR + warp_m * 32 + qm;
#pragma unroll
            for (int mt = 0; mt < 2; mt++) {
                uint32_t af[4];
                const uint32_t* a0 = ap + mt * 16;
                af[0] = a0[0];
                af[1] = a0[8];
                af[2] = a0[4 * ASTR];
                af[3] = a0[4 * ASTR + 8];
#pragma unroll
                for (int nt = 0; nt < 8; nt++)
                    mma_tf32(d[mt][nt], af, bu[nt], bu[8 + nt]);
            }
        }
    }
    CPA_WAIT0();

    // ---- epilogue: z = D + bias + res ; LN ; relu ; store -----------------
    const float* hin_b = hin + ((size_t)b * NN + j0) * DD;
    float* hout_b = hout + ((size_t)b * NN + j0) * DD;

#pragma unroll
    for (int mt = 0; mt < 2; mt++)
#pragma unroll
        for (int h = 0; h < 2; h++) {
            int jl = warp_m * 32 + mt * 16 + h * 8 + qm;
            const float* rrow = hin_b + (size_t)jl * DD;
            float s = 0.f, q = 0.f;
#pragma unroll
            for (int nt = 0; nt < 8; nt++) {
                int e = warp_n * 64 + nt * 8 + qn * 2;
                float2 rv = *(const float2*)(rrow + e);
                float z0 = d[mt][nt][2 * h + 0] + bias_s[e + 0] + rv.x;
                float z1 = d[mt][nt][2 * h + 1] + bias_s[e + 1] + rv.y;
                d[mt][nt][2 * h + 0] = z0;
                d[mt][nt][2 * h + 1] = z1;
                s += z0 + z1;
                q += z0 * z0 + z1 * z1;
            }
            s += __shfl_xor_sync(0xffffffffu, s, 1);
            s += __shfl_xor_sync(0xffffffffu, s, 2);
            q += __shfl_xor_sync(0xffffffffu, q, 1);
            q += __shfl_xor_sync(0xffffffffu, q, 2);
            if (qn == 0) {
                red_s[jl][warp_n][0] = s;
                red_s[jl][warp_n][1] = q;
            }
        }
    __syncthreads();

#pragma unroll
    for (int mt = 0; mt < 2; mt++)
#pragma unroll
        for (int h = 0; h < 2; h++) {
            int jl = warp_m * 32 + mt * 16 + h * 8 + qm;
            float s = red_s[jl][0][0] + red_s[jl][1][0];
            float q = red_s[jl][0][1] + red_s[jl][1][1];
            float mu = s * (1.0f / DD);
            float var = q * (1.0f / DD) - mu * mu;
            float rstd = rsqrtf(var + 1e-5f);
            float* orow = hout_b + (size_t)jl * DD;
#pragma unroll
            for (int nt = 0; nt < 8; nt++) {
                int e = warp_n * 64 + nt * 8 + qn * 2;
                float2 o;
                o.x = fmaxf(0.f, (d[mt][nt][2 * h + 0] - mu) * rstd * gamma_s[e + 0] + beta_s[e + 0]);
                o.y = fmaxf(0.f, (d[mt][nt][2 * h + 1] - mu) * rstd * gamma_s[e + 1] + beta_s[e + 1]);
                *(float2*)(orow + e) = o;
            }
        }
}

// ---------------------------------------------------------------------------
extern "C" void kernel_launch(void* const* d_in, const int* in_sizes, int n_in,
                              void* d_out, int out_size) {
    (void)in_sizes; (void)n_in; (void)out_size;
    const float* X      = (const float*)d_in[0];
    const float* adj    = (const float*)d_in[1];
    const float* Ws     = (const float*)d_in[2];
    const float* bs     = (const float*)d_in[3];
    const float* gammas = (const float*)d_in[4];
    const float* betas  = (const float*)d_in[5];
    float* out = (float*)d_out;

    float *hw, *h0, *h1;
    cudaGetSymbolAddress((void**)&hw, g_hw);
    cudaGetSymbolAddress((void**)&h0, g_h0);
    cudaGetSymbolAddress((void**)&h1, g_h1);

    static int configured = 0;
    if (!configured) {
        cudaFuncSetAttribute(gcn_kernel,
                             cudaFuncAttributeMaxDynamicSharedMemorySize,
                             DYN_SMEM);
        configured = 1;
    }

    const float* hsrc = X;
    for (int l = 0; l < 3; l++) {
        float* hdst = (l == 2) ? out : (l == 0 ? h0 : h1);
        linear_kernel<<<(BATCH * NN) / 128, 256>>>(
            hsrc, Ws + (size_t)l * DD * DD, hw);
        gcn_kernel<<<dim3(NN / CTJ, BATCH), 256, DYN_SMEM>>>(
            adj, hw, hsrc, hdst,
            bs + (size_t)l * DD, gammas + (size_t)l * DD,
            betas + (size_t)l * DD);
        hsrc = hdst;
    }
}

// round 12
// speedup vs baseline: 1.8523x; 1.1777x over previous
#include <cuda_runtime.h>
#include <cstdint>

// WaveGNN: B=16, N=2048, D=128, L=3
//   per layer: hw = h @ W ; agg = adj^T @ hw ; h = relu(LN(agg + b + h))
// Both GEMMs on tensor cores via generic-target mma.sync tf32 (m16n8k8).
// R12: R11 + the missing __syncthreads() after CPA_WAIT0 in linear_mma's
//      pipeline tail (cross-thread cp.async visibility race -> 1.9e-2 err).

#define BATCH 16
#define NN    2048
#define DD    128

// gcn tiling
#define CTJ   128          // j rows per CTA
#define KC    32           // K (i) rows per pipeline chunk
#define NKC   (NN / KC)    // 64 chunks
#define ASTR  136          // adj tile stride (8qn+qm distinct banks)
#define A_FLOATS (KC * ASTR)          // 4352
#define B_FLOATS (KC * DD)            // 4096 (frag layout, no padding)
#define STG_F (A_FLOATS + B_FLOATS)   // 8448 floats/stage
#define NSTG  3
#define DYN_SMEM (NSTG * STG_F * 4)   // 101376 bytes -> 2 CTAs/SM

// linear tiling
#define LW_STR 136
#define LH_STR 36
#define LW_FLOATS (DD * LW_STR)            // 17408
#define LH_FLOATS (DD * LH_STR)            // 4608 per stage (128 rows x 32+4)
#define DYN_L ((LW_FLOATS + 2 * LH_FLOATS) * 4)   // 106496 bytes

typedef unsigned long long u64;

// ---------------- scratch (static device globals; no runtime alloc) --------
__device__ float g_hw[BATCH * NN * DD];   // B-FRAGMENT layout (see below)
__device__ float g_h0[BATCH * NN * DD];
__device__ float g_h1[BATCH * NN * DD];

// hw fragment layout, per batch b, per 32-row i-chunk c, value hw[i][e]:
//   ic=i%32, kk=ic/8, kr=ic%8, qn=kr&3, h=kr>>2
//   wn=e>>6, nl=e&63, qm=nl&7, nt=nl>>3
//   lane=qm*4+qn, s=nt*2+h, s4=s>>2, sl=s&3, sw=(lane>>1)&3
//   off = (b*64+c)*4096 + (wn*4+kk)*512 + lane*16 + ((s4^sw)<<2) + sl
// One LDS.128 per lane yields (b0,b1) for two consecutive nt.

// ---------------- helpers ---------------------------------------------------
__device__ __forceinline__ uint32_t smem_u32(const void* p) {
    uint32_t a;
    asm("{ .reg .u64 t; cvta.to.shared.u64 t, %1; cvt.u32.u64 %0, t; }"
        : "=r"(a) : "l"(p));
    return a;
}

__device__ __forceinline__ void cpa16(uint32_t dst, const void* src) {
    asm volatile("cp.async.cg.shared.global [%0], [%1], 16;"
                 :: "r"(dst), "l"(src) : "memory");
}
#define CPA_COMMIT() asm volatile("cp.async.commit_group;" ::: "memory")
#define CPA_WAIT1()  asm volatile("cp.async.wait_group 1;" ::: "memory")
#define CPA_WAIT0()  asm volatile("cp.async.wait_group 0;" ::: "memory")

__device__ __forceinline__ void mma_tf32(float* d, const uint32_t* a,
                                         const uint32_t b0, const uint32_t b1) {
    asm volatile(
        "mma.sync.aligned.m16n8k8.row.col.f32.tf32.tf32.f32 "
        "{%0,%1,%2,%3}, {%4,%5,%6,%7}, {%8,%9}, {%0,%1,%2,%3};"
        : "+f"(d[0]), "+f"(d[1]), "+f"(d[2]), "+f"(d[3])
        : "r"(a[0]), "r"(a[1]), "r"(a[2]), "r"(a[3]), "r"(b0), "r"(b1));
}

__device__ __forceinline__ float tf32_rna(float v) {
    uint32_t u;
    asm("cvt.rna.tf32.f32 %0, %1;" : "=r"(u) : "f"(v));
    return __uint_as_float(u);
}

// ---------------------------------------------------------------------------
// linear_mma: hw[m,e] = sum_k h[m,k] * W[k,e]  (tf32 mma, K=128)
// grid 256 x 256 thr; CTA 128m x 128e; warp tile 32x64 (4m x 2n warps).
// Epilogue scatters tf32-rounded results into the B-fragment layout.
// ---------------------------------------------------------------------------
__global__ void __launch_bounds__(256, 2)
linear_mma(const float* __restrict__ h, const float* __restrict__ W,
           float* __restrict__ out) {
    extern __shared__ float lsm[];
    float* Ws_s = lsm;                       // [128][LW_STR]
    float* Hs0 = lsm + LW_FLOATS;            // [128][LH_STR] x2 stages
    float* Hs1 = Hs0 + LH_FLOATS;

    const int tid = threadIdx.x;
    const int lane = tid & 31;
    const int wid = tid >> 5;
    const int warp_m = wid & 3;
    const int warp_n = wid >> 2;
    const int qm = lane >> 2;
    const int qn = lane & 3;
    const int m0 = blockIdx.x * 128;
    const uint32_t smem_b = smem_u32(lsm);

    // h chunk loader: 128 rows x 32 k-floats into Hs[stage]
    const float* h_src = h + (size_t)(m0 + (tid >> 3)) * DD + (tid & 7) * 4;
    uint32_t h_doff = ((tid >> 3) * LH_STR + (tid & 7) * 4) * 4;
    auto load_h = [&](int kt, int st) {
        uint32_t base = smem_b + (uint32_t)(LW_FLOATS + st * LH_FLOATS) * 4 + h_doff;
        const float* src = h_src + kt * KC;
#pragma unroll
        for (int p = 0; p < 4; p++)
            cpa16(base + (uint32_t)(p * 32 * LH_STR) * 4, src + (size_t)(p * 32) * DD);
        CPA_COMMIT();
    };

    load_h(0, 0);
    load_h(1, 1);

    // preload W (tf32-rna rounded)
#pragma unroll
    for (int p = 0; p < 16; p++) {
        int v = tid + p * 256;
        int k = v >> 5, e4 = (v & 31) * 4;
        float4 w = *(const float4*)(W + (size_t)k * DD + e4);
        float* dst = Ws_s + k * LW_STR + e4;
        dst[0] = tf32_rna(w.x);
        dst[1] = tf32_rna(w.y);
        dst[2] = tf32_rna(w.z);
        dst[3] = tf32_rna(w.w);
    }

    float d[2][8][4];
#pragma unroll
    for (int mt = 0; mt < 2; mt++)
#pragma unroll
        for (int nt = 0; nt < 8; nt++)
#pragma unroll
            for (int c = 0; c < 4; c++) d[mt][nt][c] = 0.f;

    CPA_WAIT1();
    __syncthreads();

    const uint32_t* Wu = (const uint32_t*)Ws_s;

    for (int kt = 0; kt < 4; kt++) {
        const uint32_t* Hu = (const uint32_t*)((kt & 1) ? Hs1 : Hs0);
#pragma unroll
        for (int kk = 0; kk < 4; kk++) {
            const uint32_t* ap = Hu + (warp_m * 32 + qm) * LH_STR + kk * 8 + qn;
            uint32_t af0[4] = {ap[0], ap[8 * LH_STR], ap[4], ap[8 * LH_STR + 4]};
            const uint32_t* ap1 = ap + 16 * LH_STR;
            uint32_t af1[4] = {ap1[0], ap1[8 * LH_STR], ap1[4], ap1[8 * LH_STR + 4]};

            const uint32_t* bp = Wu + (kt * KC + kk * 8 + qn) * LW_STR +
                                 warp_n * 64 + qm;
#pragma unroll
            for (int nt = 0; nt < 8; nt++) {
                uint32_t b0 = bp[nt * 8];
                uint32_t b1 = bp[4 * LW_STR + nt * 8];
                mma_tf32(d[0][nt], af0, b0, b1);
                mma_tf32(d[1][nt], af1, b0, b1);
            }
        }
        if (kt + 2 < 4) {
            __syncthreads();            // all warps done reading stage kt&1
            load_h(kt + 2, kt & 1);
            CPA_WAIT1();                // chunk kt+1 landed (own copies)
            __syncthreads();            // ... and everyone else's
        } else if (kt + 1 < 4) {
            CPA_WAIT0();                // last chunk's copies (own)
            __syncthreads();            // FIX: make peers' copies visible
        }
    }

    // ---- epilogue: scatter tf32-rounded into B-fragment layout ------------
    const int bb = m0 >> 11;                   // batch (128 | 2048)
#pragma unroll
    for (int mt = 0; mt < 2; mt++)
#pragma unroll
        for (int hh = 0; hh < 2; hh++) {
            int i_glob = m0 + warp_m * 32 + mt * 16 + hh * 8 + qm;
            int il = i_glob & (NN - 1);
            int chunk = il >> 5;
            int ic = il & 31;
            int kko = ic >> 3;
            int kr = ic & 7;
            int qi = kr & 3;
            int hi = kr >> 2;
            size_t cbase = ((size_t)(bb * 64 + chunk)) * 4096 +
                           (size_t)((warp_n * 4 + kko) * 512);
#pragma unroll
            for (int cl = 0; cl < 2; cl++) {
                int lane_ = (qn * 2 + cl) * 4 + qi;
                int sw_ = (lane_ >> 1) & 3;
                size_t lbase = cbase + lane_ * 16;
#pragma unroll
                for (int nt = 0; nt < 8; nt++) {
                    int s = nt * 2 + hi;
                    int s4 = s >> 2, sl = s & 3;
                    out[lbase + ((s4 ^ sw_) << 2) + sl] =
                        tf32_rna(d[mt][nt][hh * 2 + cl]);
                }
            }
        }
}

// ---------------------------------------------------------------------------
// gcn_kernel (tf32 mma.sync):
//   D[j,e] = sum_i adj[b,i,j] * hw[b,i,e]
//   out = relu(LN(D + bias + hin))
// grid (NN/CTJ=16, BATCH) x 256 threads; 8 warps, warp tile 32x64 (4m x 2n)
// ---------------------------------------------------------------------------
__global__ void __launch_bounds__(256, 2)
gcn_kernel(const float* __restrict__ adj, const float* __restrict__ hw,
           const float* __restrict__ hin, float* __restrict__ hout,
           const float* __restrict__ bias, const float* __restrict__ gamma,
           const float* __restrict__ beta) {
    extern __shared__ float smem[];
    __shared__ float red_s[CTJ][2][2];
    __shared__ float bias_s[DD], gamma_s[DD], beta_s[DD];

    const int tid = threadIdx.x;
    const int lane = tid & 31;
    const int wid = tid >> 5;
    const int warp_m = wid & 3;      // 4 m-warps x 32 rows
    const int warp_n = wid >> 2;     // 2 n-warps x 64 cols
    const int qm = lane >> 2;        // 0..7
    const int qn = lane & 3;         // 0..3
    const int sw = (lane >> 1) & 3;  // B-frag xor swizzle
    const int b = blockIdx.y;
    const int j0 = blockIdx.x * CTJ;

    if (tid < DD) {
        bias_s[tid] = bias[tid];
        gamma_s[tid] = gamma[tid];
        beta_s[tid] = beta[tid];
    }

    const uint32_t smem_b = smem_u32(smem);

    float d[2][8][4];
#pragma unroll
    for (int mt = 0; mt < 2; mt++)
#pragma unroll
        for (int nt = 0; nt < 8; nt++)
#pragma unroll
            for (int c = 0; c < 4; c++) d[mt][nt][c] = 0.f;

    // ---- chunk loader: all addressing hoisted into incrementing regs ------
    const float* a_src = adj + (size_t)b * NN * NN + (size_t)(tid >> 5) * NN +
                         j0 + (tid & 31) * 4;
    const float* b_src = hw + (size_t)b * NN * DD + tid * 4;
    const uint32_t a_doff = (uint32_t)((tid >> 5) * ASTR + (tid & 31) * 4) * 4;
    const uint32_t b_doff = (uint32_t)tid * 16;

    auto load_chunk = [&](int st) {
        uint32_t a_base = smem_b + (uint32_t)(st * STG_F) * 4 + a_doff;
        uint32_t b_base = smem_b + (uint32_t)(st * STG_F + A_FLOATS) * 4 + b_doff;
#pragma unroll
        for (int p = 0; p < 4; p++)
            cpa16(a_base + (uint32_t)(p * 8 * ASTR) * 4, a_src + (size_t)(p * 8) * NN);
#pragma unroll
        for (int p = 0; p < 4; p++)
            cpa16(b_base + (uint32_t)(p * 4096), b_src + p * 1024);
        CPA_COMMIT();
        a_src += (size_t)KC * NN;
        b_src += B_FLOATS;
    };

    load_chunk(0);
    load_chunk(1);

    int cs = 0, ls = 2;
    for (int kt = 0; kt < NKC; kt++) {
        CPA_WAIT1();
        __syncthreads();
        if (kt + 2 < NKC) {
            load_chunk(ls);
            ls = (ls == NSTG - 1) ? 0 : ls + 1;
        }

        const float* As = smem + cs * STG_F;
        const float* Bs = As + A_FLOATS;
        cs = (cs == NSTG - 1) ? 0 : cs + 1;
        const uint32_t* Asu = (const uint32_t*)As;

#pragma unroll
        for (int kk = 0; kk < KC / 8; kk++) {
            const uint32_t* ap = Asu + (kk * 8 + qn) * ASTR + warp_m * 32 + qm;
            uint32_t af0[4] = {ap[0], ap[8], ap[4 * ASTR], ap[4 * ASTR + 8]};
            uint32_t af1[4] = {ap[16], ap[24], ap[4 * ASTR + 16], ap[4 * ASTR + 24]};

            const float4* bp = (const float4*)(Bs + (warp_n * 4 + kk) * 512) +
                               lane * 4;
#pragma unroll
            for (int i = 0; i < 4; i++) {
                float4 bq = bp[i ^ sw];
                uint32_t b0 = __float_as_uint(bq.x);
                uint32_t b1 = __float_as_uint(bq.y);
                uint32_t b2 = __float_as_uint(bq.z);
                uint32_t b3 = __float_as_uint(bq.w);
                mma_tf32(d[0][2 * i + 0], af0, b0, b1);
                mma_tf32(d[0][2 * i + 1], af0, b2, b3);
                mma_tf32(d[1][2 * i + 0], af1, b0, b1);
                mma_tf32(d[1][2 * i + 1], af1, b2, b3);
            }
        }
    }
    CPA_WAIT0();

    // ---- epilogue: z = D + bias + res ; LN ; relu ; store -----------------
    const float* hin_b = hin + ((size_t)b * NN + j0) * DD;
    float* hout_b = hout + ((size_t)b * NN + j0) * DD;

#pragma unroll
    for (int mt = 0; mt < 2; mt++)
#pragma unroll
        for (int h = 0; h < 2; h++) {
            int jl = warp_m * 32 + mt * 16 + h * 8 + qm;
            const float* rrow = hin_b + (size_t)jl * DD;
            float s = 0.f, q = 0.f;
#pragma unroll
            for (int nt = 0; nt < 8; nt++) {
                int e = warp_n * 64 + nt * 8 + qn * 2;
                float2 rv = *(const float2*)(rrow + e);
                float z0 = d[mt][nt][2 * h + 0] + bias_s[e + 0] + rv.x;
                float z1 = d[mt][nt][2 * h + 1] + bias_s[e + 1] + rv.y;
                d[mt][nt][2 * h + 0] = z0;
                d[mt][nt][2 * h + 1] = z1;
                s += z0 + z1;
                q += z0 * z0 + z1 * z1;
            }
            s += __shfl_xor_sync(0xffffffffu, s, 1);
            s += __shfl_xor_sync(0xffffffffu, s, 2);
            q += __shfl_xor_sync(0xffffffffu, q, 1);
            q += __shfl_xor_sync(0xffffffffu, q, 2);
            if (qn == 0) {
                red_s[jl][warp_n][0] = s;
                red_s[jl][warp_n][1] = q;
            }
        }
    __syncthreads();

#pragma unroll
    for (int mt = 0; mt < 2; mt++)
#pragma unroll
        for (int h = 0; h < 2; h++) {
            int jl = warp_m * 32 + mt * 16 + h * 8 + qm;
            float s = red_s[jl][0][0] + red_s[jl][1][0];
            float q = red_s[jl][0][1] + red_s[jl][1][1];
            float mu = s * (1.0f / DD);
            float var = q * (1.0f / DD) - mu * mu;
            float rstd = rsqrtf(var + 1e-5f);
            float* orow = hout_b + (size_t)jl * DD;
#pragma unroll
            for (int nt = 0; nt < 8; nt++) {
                int e = warp_n * 64 + nt * 8 + qn * 2;
                float2 o;
                o.x = fmaxf(0.f, (d[mt][nt][2 * h + 0] - mu) * rstd * gamma_s[e + 0] + beta_s[e + 0]);
                o.y = fmaxf(0.f, (d[mt][nt][2 * h + 1] - mu) * rstd * gamma_s[e + 1] + beta_s[e + 1]);
                *(float2*)(orow + e) = o;
            }
        }
}

// ---------------------------------------------------------------------------
extern "C" void kernel_launch(void* const* d_in, const int* in_sizes, int n_in,
                              void* d_out, int out_size) {
    (void)in_sizes; (void)n_in; (void)out_size;
    const float* X      = (const float*)d_in[0];
    const float* adj    = (const float*)d_in[1];
    const float* Ws     = (const float*)d_in[2];
    const float* bs     = (const float*)d_in[3];
    const float* gammas = (const float*)d_in[4];
    const float* betas  = (const float*)d_in[5];
    float* out = (float*)d_out;

    float *hw, *h0, *h1;
    cudaGetSymbolAddress((void**)&hw, g_hw);
    cudaGetSymbolAddress((void**)&h0, g_h0);
    cudaGetSymbolAddress((void**)&h1, g_h1);

    static int configured = 0;
    if (!configured) {
        cudaFuncSetAttribute(gcn_kernel,
                             cudaFuncAttributeMaxDynamicSharedMemorySize,
                             DYN_SMEM);
        cudaFuncSetAttribute(linear_mma,
                             cudaFuncAttributeMaxDynamicSharedMemorySize,
                             DYN_L);
        configured = 1;
    }

    const float* hsrc = X;
    for (int l = 0; l < 3; l++) {
        float* hdst = (l == 2) ? out : (l == 0 ? h0 : h1);
        linear_mma<<<(BATCH * NN) / 128, 256, DYN_L>>>(
            hsrc, Ws + (size_t)l * DD * DD, hw);
        gcn_kernel<<<dim3(NN / CTJ, BATCH), 256, DYN_SMEM>>>(
            adj, hw, hsrc, hdst,
            bs + (size_t)l * DD, gammas + (size_t)l * DD,
            betas + (size_t)l * DD);
        hsrc = hdst;
    }
}